// round 1
// baseline (speedup 1.0000x reference)
#include <cuda_runtime.h>

#define TT 2048
#define DD 1024
#define HH 16

// ---------------- scratch (static device globals; no allocations) -------------
__device__ float g_qkv[TT * 3 * DD];     // [t][3*1024]  (q|k|v per token)
__device__ float g_kvgeo[TT * 2 * DD];   // [t][2*1024]  (k_geo|v_geo)
__device__ float g_jw[HH * 6 * TT];      // [h][c][t]    J6-applied write lines
__device__ float g_read[TT * HH * 6];    // [t][h][c]    read lines
__device__ float g_gate[HH * TT];        // [h][t]       gram gate
__device__ float g_kenh[HH * TT * 64];   // [h][t][d]
__device__ float g_venh[HH * TT * 64];   // [h][t][d]
__device__ float g_attno[TT * DD];       // [t][h*64+d]  attention output

// ---------------- generic SGEMM: C[M,N] = A[M,K] @ B[K,N] (+bias) ------------
// M,N multiples of 64, K multiple of 16. Row-major everything.
__global__ __launch_bounds__(256) void sgemm64(
    const float* __restrict__ A, const float* __restrict__ B,
    const float* __restrict__ bias, float* __restrict__ C,
    int M, int N, int K)
{
    __shared__ float As[16][64];
    __shared__ float Bs[16][64];
    const int tid = threadIdx.x;
    const int m0 = blockIdx.y << 6, n0 = blockIdx.x << 6;
    const int ty = tid >> 4, tx = tid & 15;

    const int arow = tid >> 2, acol = (tid & 3) << 2;
    const int brow = tid >> 4, bcol = (tid & 15) << 2;
    const float* Ap = A + (size_t)(m0 + arow) * K + acol;
    const float* Bp = B + (size_t)brow * N + n0 + bcol;

    float acc[4][4];
#pragma unroll
    for (int i = 0; i < 4; i++)
#pragma unroll
        for (int j = 0; j < 4; j++) acc[i][j] = 0.f;

    for (int kt = 0; kt < K; kt += 16) {
        float4 av = *(const float4*)(Ap + kt);
        float4 bv = *(const float4*)(Bp + (size_t)kt * N);
        __syncthreads();
        As[acol + 0][arow] = av.x;
        As[acol + 1][arow] = av.y;
        As[acol + 2][arow] = av.z;
        As[acol + 3][arow] = av.w;
        *(float4*)&Bs[brow][bcol] = bv;
        __syncthreads();
#pragma unroll
        for (int k = 0; k < 16; k++) {
            float4 a = *(const float4*)&As[k][ty << 2];
            float4 b = *(const float4*)&Bs[k][tx << 2];
            acc[0][0] += a.x * b.x; acc[0][1] += a.x * b.y; acc[0][2] += a.x * b.z; acc[0][3] += a.x * b.w;
            acc[1][0] += a.y * b.x; acc[1][1] += a.y * b.y; acc[1][2] += a.y * b.z; acc[1][3] += a.y * b.w;
            acc[2][0] += a.z * b.x; acc[2][1] += a.z * b.y; acc[2][2] += a.z * b.z; acc[2][3] += a.z * b.w;
            acc[3][0] += a.w * b.x; acc[3][1] += a.w * b.y; acc[3][2] += a.w * b.z; acc[3][3] += a.w * b.w;
        }
    }
    float4 bb = make_float4(0.f, 0.f, 0.f, 0.f);
    if (bias) bb = *(const float4*)&bias[n0 + (tx << 2)];
#pragma unroll
    for (int i = 0; i < 4; i++) {
        float4 o;
        o.x = acc[i][0] + bb.x; o.y = acc[i][1] + bb.y;
        o.z = acc[i][2] + bb.z; o.w = acc[i][3] + bb.w;
        *(float4*)&C[(size_t)(m0 + (ty << 2) + i) * N + n0 + (tx << 2)] = o;
    }
}

// ------------- fused: 4 small projections + Plucker lines per token ----------
__global__ __launch_bounds__(256) void proj_lines(
    const float* __restrict__ x,
    const float* __restrict__ w1w, const float* __restrict__ w2w,
    const float* __restrict__ w1r, const float* __restrict__ w2r)
{
    const int t = blockIdx.x, tid = threadIdx.x;
    __shared__ float xa[DD];      // x[t]
    __shared__ float xb[DD];      // x[t-1] (zeros at t==0)
    __shared__ float proj[4][64]; // w1,w2,r1,r2

    {
        int i = tid << 2;
        *(float4*)&xa[i] = *(const float4*)&x[(size_t)t * DD + i];
        if (t > 0) *(float4*)&xb[i] = *(const float4*)&x[(size_t)(t - 1) * DD + i];
        else { xb[i] = 0.f; xb[i + 1] = 0.f; xb[i + 2] = 0.f; xb[i + 3] = 0.f; }
    }
    __syncthreads();

    const int which = tid >> 6, col = tid & 63;
    const float* W = (which == 0) ? w1w : (which == 1) ? w2w : (which == 2) ? w1r : w2r;
    const float* xs = (which == 0) ? xb : xa;
    float s = 0.f;
#pragma unroll 8
    for (int k = 0; k < DD; k++) s += xs[k] * W[k * 64 + col];
    proj[which][col] = s;
    __syncthreads();

    if (tid < HH) {
        const int h = tid;
        // write line (p1 from x_prev, p2 from x)
        float a0 = proj[0][h * 4 + 0], a1 = proj[0][h * 4 + 1], a2 = proj[0][h * 4 + 2], a3 = proj[0][h * 4 + 3];
        float b0 = proj[1][h * 4 + 0], b1 = proj[1][h * 4 + 1], b2 = proj[1][h * 4 + 2], b3 = proj[1][h * 4 + 3];
        float L0 = a0 * b1 - a1 * b0;
        float L1 = a0 * b2 - a2 * b0;
        float L2 = a0 * b3 - a3 * b0;
        float L3 = a1 * b2 - a2 * b1;
        float L4 = a1 * b3 - a3 * b1;
        float L5 = a2 * b3 - a3 * b2;
        float n = sqrtf(L0 * L0 + L1 * L1 + L2 * L2 + L3 * L3 + L4 * L4 + L5 * L5);
        float inv = 1.f / fmaxf(n, 1e-12f);
        float* jw = g_jw + h * 6 * TT;
        jw[0 * TT + t] =  L5 * inv;   // j = (L5,-L4,L3,L2,-L1,L0)
        jw[1 * TT + t] = -L4 * inv;
        jw[2 * TT + t] =  L3 * inv;
        jw[3 * TT + t] =  L2 * inv;
        jw[4 * TT + t] = -L1 * inv;
        jw[5 * TT + t] =  L0 * inv;
        // read line
        a0 = proj[2][h * 4 + 0]; a1 = proj[2][h * 4 + 1]; a2 = proj[2][h * 4 + 2]; a3 = proj[2][h * 4 + 3];
        b0 = proj[3][h * 4 + 0]; b1 = proj[3][h * 4 + 1]; b2 = proj[3][h * 4 + 2]; b3 = proj[3][h * 4 + 3];
        L0 = a0 * b1 - a1 * b0;
        L1 = a0 * b2 - a2 * b0;
        L2 = a0 * b3 - a3 * b0;
        L3 = a1 * b2 - a2 * b1;
        L4 = a1 * b3 - a3 * b1;
        L5 = a2 * b3 - a3 * b2;
        n = sqrtf(L0 * L0 + L1 * L1 + L2 * L2 + L3 * L3 + L4 * L4 + L5 * L5);
        inv = 1.f / fmaxf(n, 1e-12f);
        float* rd = g_read + ((size_t)t * HH + h) * 6;
        rd[0] = L0 * inv; rd[1] = L1 * inv; rd[2] = L2 * inv;
        rd[3] = L3 * inv; rd[4] = L4 * inv; rd[5] = L5 * inv;
    }
}

// ------------- mem_score / gram gate: per (t,h) decayed incidence^2 ----------
__global__ __launch_bounds__(128) void memscore(
    const float* __restrict__ decay_logits, const float* __restrict__ mem_scale)
{
    const int t = blockIdx.x, h = blockIdx.y, tid = threadIdx.x;
    const float* rd = g_read + ((size_t)t * HH + h) * 6;
    const float r0 = rd[0], r1 = rd[1], r2 = rd[2], r3 = rd[3], r4 = rd[4], r5 = rd[5];

    const float logit = decay_logits[h];
    const float decay = 1.f / (1.f + expf(-logit));
    const float dlog = logf(decay);
    float w = expf((float)(tid + 1) * dlog);   // decay^(t-s) for first s
    const float d128 = expf(128.f * dlog);     // per-stride multiplier

    const float* base = g_jw + h * 6 * TT;
    float partial = 0.f;
    for (int s = t - 1 - tid; s >= 0; s -= 128) {
        float inc = r0 * base[s] + r1 * base[TT + s] + r2 * base[2 * TT + s]
                  + r3 * base[3 * TT + s] + r4 * base[4 * TT + s] + r5 * base[5 * TT + s];
        partial += inc * inc * w;
        w *= d128;
    }
#pragma unroll
    for (int o = 16; o > 0; o >>= 1) partial += __shfl_xor_sync(0xffffffffu, partial, o);
    __shared__ float red[4];
    if ((tid & 31) == 0) red[tid >> 5] = partial;
    __syncthreads();
    if (tid == 0) {
        float ms = red[0] + red[1] + red[2] + red[3];
        g_gate[h * TT + t] = 1.f / (1.f + expf(-ms * mem_scale[h]));
    }
}

// ------------- k_enh / v_enh assembly ([h][t][d] layout) ---------------------
__global__ __launch_bounds__(256) void enhance(const float* __restrict__ kv_gate_p)
{
    const int idx = blockIdx.x * 256 + threadIdx.x;  // over H*T*64
    const int d = idx & 63, t = (idx >> 6) & (TT - 1), h = idx >> 17;
    const float gg = kv_gate_p[0] * g_gate[h * TT + t];
    const float kg = g_kvgeo[(size_t)t * 2 * DD + h * 64 + d];
    const float vg = g_kvgeo[(size_t)t * 2 * DD + DD + h * 64 + d];
    g_kenh[idx] = g_qkv[(size_t)t * 3 * DD + DD + h * 64 + d] + gg * kg;
    g_venh[idx] = g_qkv[(size_t)t * 3 * DD + 2 * DD + h * 64 + d] + gg * vg;
}

// ------------- causal flash attention, fp32 ----------------------------------
// grid (T/64, H), 256 threads. Thread quad (4 threads) per query row:
//   scores: thread g owns keys s = jj*4+g ; output dims d = blk*16 + g*4 + c.
#define KS_STRIDE 72
__global__ __launch_bounds__(256) void attn()
{
    __shared__ float Ks[64 * KS_STRIDE];
    __shared__ float Vs[64 * 64];
    const int h = blockIdx.y, m0 = blockIdx.x << 6;
    const int tid = threadIdx.x, m = tid >> 2, g = tid & 3;
    const int t = m0 + m;

    float q[64];
    const float* qp = g_qkv + (size_t)t * 3 * DD + h * 64;
#pragma unroll
    for (int c = 0; c < 16; c++) {
        float4 v = *(const float4*)(qp + c * 4);
        q[c * 4 + 0] = v.x * 0.125f; q[c * 4 + 1] = v.y * 0.125f;
        q[c * 4 + 2] = v.z * 0.125f; q[c * 4 + 3] = v.w * 0.125f;
    }

    float acc[16];
#pragma unroll
    for (int i = 0; i < 16; i++) acc[i] = 0.f;
    float p_l[16];
    float mrun = -1e30f, lrun = 0.f;

    const int ldr = tid >> 2, ldc = (tid & 3) << 4;

    for (int s0 = 0; s0 <= m0; s0 += 64) {
        __syncthreads();
        const float* kp = g_kenh + ((size_t)(h * TT + s0 + ldr) << 6) + ldc;
        const float* vp = g_venh + ((size_t)(h * TT + s0 + ldr) << 6) + ldc;
#pragma unroll
        for (int u = 0; u < 4; u++) {
            float4 kv = *(const float4*)(kp + u * 4);
            *(float4*)&Ks[ldr * KS_STRIDE + ldc + u * 4] = kv;
            float4 vv = *(const float4*)(vp + u * 4);
            *(float4*)&Vs[ldr * 64 + ldc + u * 4] = vv;
        }
        __syncthreads();

        // ---- scores for this thread's 16 keys ----
        float tmax = -1e30f;
#pragma unroll
        for (int jj = 0; jj < 16; jj++) {
            const int s = (jj << 2) + g;
            const float* kr = &Ks[s * KS_STRIDE];
            float sc = 0.f;
#pragma unroll
            for (int c = 0; c < 16; c++) {
                float4 kv = *(const float4*)(kr + c * 4);
                sc += q[c * 4 + 0] * kv.x + q[c * 4 + 1] * kv.y
                    + q[c * 4 + 2] * kv.z + q[c * 4 + 3] * kv.w;
            }
            if (s0 + s > t) sc = -1e30f;
            p_l[jj] = sc;
            tmax = fmaxf(tmax, sc);
        }
        tmax = fmaxf(tmax, __shfl_xor_sync(0xffffffffu, tmax, 1));
        tmax = fmaxf(tmax, __shfl_xor_sync(0xffffffffu, tmax, 2));

        const float mnew = fmaxf(mrun, tmax);
        const float corr = __expf(mrun - mnew);
        float lsum = 0.f;
#pragma unroll
        for (int jj = 0; jj < 16; jj++) {
            float p = __expf(p_l[jj] - mnew);
            p_l[jj] = p;
            lsum += p;
        }
        lsum += __shfl_xor_sync(0xffffffffu, lsum, 1);
        lsum += __shfl_xor_sync(0xffffffffu, lsum, 2);
        lrun = lrun * corr + lsum;
        mrun = mnew;
#pragma unroll
        for (int i = 0; i < 16; i++) acc[i] *= corr;

        // ---- P @ V  (p broadcast within quad via shfl) ----
#pragma unroll
        for (int jj = 0; jj < 16; jj++) {
#pragma unroll
            for (int gg = 0; gg < 4; gg++) {
                const float p = __shfl_sync(0xffffffffu, p_l[jj], gg, 4);
                const float* vr = &Vs[((jj << 2) + gg) * 64 + (g << 2)];
#pragma unroll
                for (int blk = 0; blk < 4; blk++) {
                    float4 vv = *(const float4*)(vr + blk * 16);
                    acc[blk * 4 + 0] += p * vv.x;
                    acc[blk * 4 + 1] += p * vv.y;
                    acc[blk * 4 + 2] += p * vv.z;
                    acc[blk * 4 + 3] += p * vv.w;
                }
            }
        }
    }

    const float inv = 1.f / lrun;
    float* op = g_attno + (size_t)t * DD + h * 64 + (g << 2);
#pragma unroll
    for (int blk = 0; blk < 4; blk++) {
        float4 o;
        o.x = acc[blk * 4 + 0] * inv; o.y = acc[blk * 4 + 1] * inv;
        o.z = acc[blk * 4 + 2] * inv; o.w = acc[blk * 4 + 3] * inv;
        *(float4*)(op + blk * 16) = o;
    }
}

// -----------------------------------------------------------------------------
extern "C" void kernel_launch(void* const* d_in, const int* in_sizes, int n_in,
                              void* d_out, int out_size)
{
    const float* x            = (const float*)d_in[0];
    const float* qkv_w        = (const float*)d_in[1];
    const float* qkv_b        = (const float*)d_in[2];
    const float* w1_write     = (const float*)d_in[3];
    const float* w2_write     = (const float*)d_in[4];
    const float* w1_read      = (const float*)d_in[5];
    const float* w2_read      = (const float*)d_in[6];
    const float* kv_geo_w     = (const float*)d_in[7];
    const float* out_w        = (const float*)d_in[8];
    const float* out_b        = (const float*)d_in[9];
    const float* kv_gate      = (const float*)d_in[10];
    const float* mem_scale    = (const float*)d_in[11];
    const float* decay_logits = (const float*)d_in[12];
    float* out = (float*)d_out;

    float *p_qkv, *p_kvgeo, *p_attno;
    cudaGetSymbolAddress((void**)&p_qkv,   g_qkv);
    cudaGetSymbolAddress((void**)&p_kvgeo, g_kvgeo);
    cudaGetSymbolAddress((void**)&p_attno, g_attno);

    // 1. qkv = x @ qkv_w + qkv_b            [2048, 3072]
    sgemm64<<<dim3(3072 / 64, TT / 64), 256>>>(x, qkv_w, qkv_b, p_qkv, TT, 3072, DD);
    // 2. kv_geo = x @ kv_geo_w              [2048, 2048]
    sgemm64<<<dim3(2048 / 64, TT / 64), 256>>>(x, kv_geo_w, nullptr, p_kvgeo, TT, 2048, DD);
    // 3. projections + Plucker lines (read lines, J6-applied write lines)
    proj_lines<<<TT, 256>>>(x, w1_write, w2_write, w1_read, w2_read);
    // 4. decayed incidence^2 -> gram gate
    memscore<<<dim3(TT, HH), 128>>>(decay_logits, mem_scale);
    // 5. enhanced K/V
    enhance<<<(HH * TT * 64) / 256, 256>>>(kv_gate);
    // 6. causal flash attention
    attn<<<dim3(TT / 64, HH), 256>>>();
    // 7. final projection: out = attno @ out_w + out_b
    sgemm64<<<dim3(DD / 64, TT / 64), 256>>>(p_attno, out_w, out_b, out, TT, DD, DD);
}

// round 3
// speedup vs baseline: 1.5331x; 1.5331x over previous
#include <cuda_runtime.h>

#define TT 2048
#define DD 1024
#define HH 16

// ---------------- scratch (static device globals; no allocations) -------------
__device__ float g_qkv[TT * 3 * DD];     // [t][3*1024]  (q|k|v per token)
__device__ float g_kvgeo[TT * 2 * DD];   // [t][2*1024]  (k_geo|v_geo)
__device__ float g_proj[4 * TT * 64];    // P1|P2|R1|R2, each [t][64]
__device__ float g_jw[HH * 6 * TT];      // [h][c][t]    J6-applied write lines
__device__ float g_read[TT * HH * 6];    // [t][h][c]    read lines
__device__ float g_gate[HH * TT];        // [h][t]       gram gate
__device__ float g_kenh[HH * TT * 64];   // [h][t][d]
__device__ float g_venh[HH * TT * 64];   // [h][t][d]
__device__ float g_attno[TT * DD];       // [t][h*64+d]  attention output

// ---------------- tf32 helpers ----------------------------------------------
__device__ __forceinline__ unsigned f2tf(float f) {
    unsigned r;
    asm("cvt.rna.tf32.f32 %0, %1;" : "=r"(r) : "f"(f));
    return r;
}

__device__ __forceinline__ void mma_tf32(float* c, const unsigned* a, const unsigned* b) {
    asm volatile(
        "mma.sync.aligned.m16n8k8.row.col.f32.tf32.tf32.f32 "
        "{%0,%1,%2,%3}, {%4,%5,%6,%7}, {%8,%9}, {%0,%1,%2,%3};"
        : "+f"(c[0]), "+f"(c[1]), "+f"(c[2]), "+f"(c[3])
        : "r"(a[0]), "r"(a[1]), "r"(a[2]), "r"(a[3]), "r"(b[0]), "r"(b[1]));
}

// ---------------- tf32 GEMM body: C[M,N] = A[M,K] @ B[K,N] (+bias) ----------
// Block tile 128x64, 256 threads (8 warps as 4(M) x 2(N), warp tile 32x32).
// K-tile 32, register-prefetch double buffering.
// Requires: M % 128 == 0, N % 64 == 0, K % 32 == 0.
#define A_ST 36
#define B_ST 72

__device__ __forceinline__ void gemm_body(
    const float* __restrict__ A, const float* __restrict__ B,
    const float* __restrict__ bias, float* __restrict__ C,
    int M, int N, int K)
{
    __shared__ unsigned As[128 * A_ST];
    __shared__ unsigned Bs[32 * B_ST];

    const int tid = threadIdx.x;
    const int lane = tid & 31, warp = tid >> 5;
    const int wm = (warp & 3) << 5;
    const int wn = (warp >> 2) << 5;
    const int m0 = blockIdx.y << 7, n0 = blockIdx.x << 6;
    const int lr = lane >> 2, lc = lane & 3;

    // global-load assignments
    const int am = tid >> 3, ak = (tid & 7) << 2;    // A rows am+32i, k chunk ak
    const int bk = tid >> 4, bn = (tid & 15) << 2;   // B rows bk+16i, n chunk bn

    const float* Aptr = A + (size_t)(m0 + am) * K + ak;
    const float* Bptr = B + (size_t)bk * N + n0 + bn;

    float4 ar[4], br[2];
#pragma unroll
    for (int i = 0; i < 4; i++) ar[i] = *(const float4*)(Aptr + (size_t)(i * 32) * K);
#pragma unroll
    for (int i = 0; i < 2; i++) br[i] = *(const float4*)(Bptr + (size_t)(i * 16) * N);

    float acc[2][4][4];
#pragma unroll
    for (int mi = 0; mi < 2; mi++)
#pragma unroll
        for (int ni = 0; ni < 4; ni++)
#pragma unroll
            for (int q = 0; q < 4; q++) acc[mi][ni][q] = 0.f;

    for (int kt = 0; kt < K; kt += 32) {
        __syncthreads();
#pragma unroll
        for (int i = 0; i < 4; i++) {
            unsigned* p = &As[(am + i * 32) * A_ST + ak];
            p[0] = f2tf(ar[i].x); p[1] = f2tf(ar[i].y);
            p[2] = f2tf(ar[i].z); p[3] = f2tf(ar[i].w);
        }
#pragma unroll
        for (int i = 0; i < 2; i++) {
            unsigned* p = &Bs[(bk + i * 16) * B_ST + bn];
            p[0] = f2tf(br[i].x); p[1] = f2tf(br[i].y);
            p[2] = f2tf(br[i].z); p[3] = f2tf(br[i].w);
        }
        __syncthreads();
        if (kt + 32 < K) {
#pragma unroll
            for (int i = 0; i < 4; i++)
                ar[i] = *(const float4*)(Aptr + (size_t)(i * 32) * K + (kt + 32));
#pragma unroll
            for (int i = 0; i < 2; i++)
                br[i] = *(const float4*)(Bptr + (size_t)(kt + 32 + i * 16) * N);
        }
#pragma unroll
        for (int kk = 0; kk < 32; kk += 8) {
            unsigned af[2][4], bf[4][2];
#pragma unroll
            for (int mi = 0; mi < 2; mi++) {
                const int row = wm + mi * 16 + lr;
                af[mi][0] = As[row * A_ST + kk + lc];
                af[mi][1] = As[(row + 8) * A_ST + kk + lc];
                af[mi][2] = As[row * A_ST + kk + 4 + lc];
                af[mi][3] = As[(row + 8) * A_ST + kk + 4 + lc];
            }
#pragma unroll
            for (int ni = 0; ni < 4; ni++) {
                const int col = wn + ni * 8 + lr;
                bf[ni][0] = Bs[(kk + lc) * B_ST + col];
                bf[ni][1] = Bs[(kk + 4 + lc) * B_ST + col];
            }
#pragma unroll
            for (int mi = 0; mi < 2; mi++)
#pragma unroll
                for (int ni = 0; ni < 4; ni++)
                    mma_tf32(acc[mi][ni], af[mi], bf[ni]);
        }
    }

    // epilogue
#pragma unroll
    for (int mi = 0; mi < 2; mi++) {
#pragma unroll
        for (int ni = 0; ni < 4; ni++) {
            const int row = m0 + wm + mi * 16 + lr;
            const int col = n0 + wn + ni * 8 + (lc << 1);
            float b0 = 0.f, b1 = 0.f;
            if (bias) { b0 = bias[col]; b1 = bias[col + 1]; }
            float2 o0, o1;
            o0.x = acc[mi][ni][0] + b0; o0.y = acc[mi][ni][1] + b1;
            o1.x = acc[mi][ni][2] + b0; o1.y = acc[mi][ni][3] + b1;
            *(float2*)&C[(size_t)row * N + col] = o0;
            *(float2*)&C[(size_t)(row + 8) * N + col] = o1;
        }
    }
}

__global__ __launch_bounds__(256) void gemm_tf32(
    const float* __restrict__ A, const float* __restrict__ B,
    const float* __restrict__ bias, float* __restrict__ C,
    int M, int N, int K)
{
    gemm_body(A, B, bias, C, M, N, K);
}

// 4 small projections in one launch (z picks weight / output slice)
__global__ __launch_bounds__(256) void gemm_proj(
    const float* __restrict__ x,
    const float* __restrict__ w0, const float* __restrict__ w1,
    const float* __restrict__ w2, const float* __restrict__ w3)
{
    const float* B = (blockIdx.z == 0) ? w0 : (blockIdx.z == 1) ? w1
                   : (blockIdx.z == 2) ? w2 : w3;
    float* C = g_proj + (size_t)blockIdx.z * TT * 64;
    gemm_body(x, B, nullptr, C, TT, 64, DD);
}

// ------------- Plucker lines from projections --------------------------------
__global__ __launch_bounds__(256) void lines_kernel()
{
    const int idx = blockIdx.x * 256 + threadIdx.x;   // T*H
    const int h = idx & (HH - 1), t = idx >> 4;
    const float* P1 = g_proj;
    const float* P2 = g_proj + TT * 64;
    const float* R1 = g_proj + 2 * TT * 64;
    const float* R2 = g_proj + 3 * TT * 64;

    float a0 = 0.f, a1 = 0.f, a2 = 0.f, a3 = 0.f;
    if (t > 0) {
        const float* p = P1 + (size_t)(t - 1) * 64 + h * 4;
        a0 = p[0]; a1 = p[1]; a2 = p[2]; a3 = p[3];
    }
    const float* p2 = P2 + (size_t)t * 64 + h * 4;
    float b0 = p2[0], b1 = p2[1], b2 = p2[2], b3 = p2[3];

    float L0 = a0 * b1 - a1 * b0;
    float L1 = a0 * b2 - a2 * b0;
    float L2 = a0 * b3 - a3 * b0;
    float L3 = a1 * b2 - a2 * b1;
    float L4 = a1 * b3 - a3 * b1;
    float L5 = a2 * b3 - a3 * b2;
    float n = sqrtf(L0 * L0 + L1 * L1 + L2 * L2 + L3 * L3 + L4 * L4 + L5 * L5);
    float inv = 1.f / fmaxf(n, 1e-12f);
    float* jw = g_jw + h * 6 * TT;
    jw[0 * TT + t] =  L5 * inv;   // j = (L5,-L4,L3,L2,-L1,L0)
    jw[1 * TT + t] = -L4 * inv;
    jw[2 * TT + t] =  L3 * inv;
    jw[3 * TT + t] =  L2 * inv;
    jw[4 * TT + t] = -L1 * inv;
    jw[5 * TT + t] =  L0 * inv;

    const float* r1 = R1 + (size_t)t * 64 + h * 4;
    const float* r2 = R2 + (size_t)t * 64 + h * 4;
    a0 = r1[0]; a1 = r1[1]; a2 = r1[2]; a3 = r1[3];
    b0 = r2[0]; b1 = r2[1]; b2 = r2[2]; b3 = r2[3];
    L0 = a0 * b1 - a1 * b0;
    L1 = a0 * b2 - a2 * b0;
    L2 = a0 * b3 - a3 * b0;
    L3 = a1 * b2 - a2 * b1;
    L4 = a1 * b3 - a3 * b1;
    L5 = a2 * b3 - a3 * b2;
    n = sqrtf(L0 * L0 + L1 * L1 + L2 * L2 + L3 * L3 + L4 * L4 + L5 * L5);
    inv = 1.f / fmaxf(n, 1e-12f);
    float* rd = g_read + ((size_t)t * HH + h) * 6;
    rd[0] = L0 * inv; rd[1] = L1 * inv; rd[2] = L2 * inv;
    rd[3] = L3 * inv; rd[4] = L4 * inv; rd[5] = L5 * inv;
}

// ------------- mem_score / gram gate: per (t,h) decayed incidence^2 ----------
__global__ __launch_bounds__(128) void memscore(
    const float* __restrict__ decay_logits, const float* __restrict__ mem_scale)
{
    const int t = blockIdx.x, h = blockIdx.y, tid = threadIdx.x;
    const float* rd = g_read + ((size_t)t * HH + h) * 6;
    const float r0 = rd[0], r1 = rd[1], r2 = rd[2], r3 = rd[3], r4 = rd[4], r5 = rd[5];

    const float logit = decay_logits[h];
    const float decay = 1.f / (1.f + expf(-logit));
    const float dlog = logf(decay);
    float w = expf((float)(tid + 1) * dlog);
    const float d128 = expf(128.f * dlog);

    const float* base = g_jw + h * 6 * TT;
    float partial = 0.f;
    for (int s = t - 1 - tid; s >= 0; s -= 128) {
        float inc = r0 * base[s] + r1 * base[TT + s] + r2 * base[2 * TT + s]
                  + r3 * base[3 * TT + s] + r4 * base[4 * TT + s] + r5 * base[5 * TT + s];
        partial += inc * inc * w;
        w *= d128;
    }
#pragma unroll
    for (int o = 16; o > 0; o >>= 1) partial += __shfl_xor_sync(0xffffffffu, partial, o);
    __shared__ float red[4];
    if ((tid & 31) == 0) red[tid >> 5] = partial;
    __syncthreads();
    if (tid == 0) {
        float ms = red[0] + red[1] + red[2] + red[3];
        g_gate[h * TT + t] = 1.f / (1.f + expf(-ms * mem_scale[h]));
    }
}

// ------------- k_enh / v_enh assembly ([h][t][d] layout) ---------------------
__global__ __launch_bounds__(256) void enhance(const float* __restrict__ kv_gate_p)
{
    const int idx = blockIdx.x * 256 + threadIdx.x;  // over H*T*64
    const int d = idx & 63, t = (idx >> 6) & (TT - 1), h = idx >> 17;
    const float gg = kv_gate_p[0] * g_gate[h * TT + t];
    const float kg = g_kvgeo[(size_t)t * 2 * DD + h * 64 + d];
    const float vg = g_kvgeo[(size_t)t * 2 * DD + DD + h * 64 + d];
    g_kenh[idx] = g_qkv[(size_t)t * 3 * DD + DD + h * 64 + d] + gg * kg;
    g_venh[idx] = g_qkv[(size_t)t * 3 * DD + 2 * DD + h * 64 + d] + gg * vg;
}

// ------------- causal flash attention, fp32 ----------------------------------
#define KS_STRIDE 72
__global__ __launch_bounds__(256) void attn()
{
    __shared__ float Ks[64 * KS_STRIDE];
    __shared__ float Vs[64 * 64];
    const int h = blockIdx.y, m0 = blockIdx.x << 6;
    const int tid = threadIdx.x, m = tid >> 2, g = tid & 3;
    const int t = m0 + m;

    float q[64];
    const float* qp = g_qkv + (size_t)t * 3 * DD + h * 64;
#pragma unroll
    for (int c = 0; c < 16; c++) {
        float4 v = *(const float4*)(qp + c * 4);
        q[c * 4 + 0] = v.x * 0.125f; q[c * 4 + 1] = v.y * 0.125f;
        q[c * 4 + 2] = v.z * 0.125f; q[c * 4 + 3] = v.w * 0.125f;
    }

    float acc[16];
#pragma unroll
    for (int i = 0; i < 16; i++) acc[i] = 0.f;
    float p_l[16];
    float mrun = -1e30f, lrun = 0.f;

    const int ldr = tid >> 2, ldc = (tid & 3) << 4;

    for (int s0 = 0; s0 <= m0; s0 += 64) {
        __syncthreads();
        const float* kp = g_kenh + ((size_t)(h * TT + s0 + ldr) << 6) + ldc;
        const float* vp = g_venh + ((size_t)(h * TT + s0 + ldr) << 6) + ldc;
#pragma unroll
        for (int u = 0; u < 4; u++) {
            float4 kv = *(const float4*)(kp + u * 4);
            *(float4*)&Ks[ldr * KS_STRIDE + ldc + u * 4] = kv;
            float4 vv = *(const float4*)(vp + u * 4);
            *(float4*)&Vs[ldr * 64 + ldc + u * 4] = vv;
        }
        __syncthreads();

        float tmax = -1e30f;
#pragma unroll
        for (int jj = 0; jj < 16; jj++) {
            const int s = (jj << 2) + g;
            const float* kr = &Ks[s * KS_STRIDE];
            float sc = 0.f;
#pragma unroll
            for (int c = 0; c < 16; c++) {
                float4 kv = *(const float4*)(kr + c * 4);
                sc += q[c * 4 + 0] * kv.x + q[c * 4 + 1] * kv.y
                    + q[c * 4 + 2] * kv.z + q[c * 4 + 3] * kv.w;
            }
            if (s0 + s > t) sc = -1e30f;
            p_l[jj] = sc;
            tmax = fmaxf(tmax, sc);
        }
        tmax = fmaxf(tmax, __shfl_xor_sync(0xffffffffu, tmax, 1));
        tmax = fmaxf(tmax, __shfl_xor_sync(0xffffffffu, tmax, 2));

        const float mnew = fmaxf(mrun, tmax);
        const float corr = __expf(mrun - mnew);
        float lsum = 0.f;
#pragma unroll
        for (int jj = 0; jj < 16; jj++) {
            float p = __expf(p_l[jj] - mnew);
            p_l[jj] = p;
            lsum += p;
        }
        lsum += __shfl_xor_sync(0xffffffffu, lsum, 1);
        lsum += __shfl_xor_sync(0xffffffffu, lsum, 2);
        lrun = lrun * corr + lsum;
        mrun = mnew;
#pragma unroll
        for (int i = 0; i < 16; i++) acc[i] *= corr;

#pragma unroll
        for (int jj = 0; jj < 16; jj++) {
#pragma unroll
            for (int gg = 0; gg < 4; gg++) {
                const float p = __shfl_sync(0xffffffffu, p_l[jj], gg, 4);
                const float* vr = &Vs[((jj << 2) + gg) * 64 + (g << 2)];
#pragma unroll
                for (int blk = 0; blk < 4; blk++) {
                    float4 vv = *(const float4*)(vr + blk * 16);
                    acc[blk * 4 + 0] += p * vv.x;
                    acc[blk * 4 + 1] += p * vv.y;
                    acc[blk * 4 + 2] += p * vv.z;
                    acc[blk * 4 + 3] += p * vv.w;
                }
            }
        }
    }

    const float inv = 1.f / lrun;
    float* op = g_attno + (size_t)t * DD + h * 64 + (g << 2);
#pragma unroll
    for (int blk = 0; blk < 4; blk++) {
        float4 o;
        o.x = acc[blk * 4 + 0] * inv; o.y = acc[blk * 4 + 1] * inv;
        o.z = acc[blk * 4 + 2] * inv; o.w = acc[blk * 4 + 3] * inv;
        *(float4*)(op + blk * 16) = o;
    }
}

// -----------------------------------------------------------------------------
extern "C" void kernel_launch(void* const* d_in, const int* in_sizes, int n_in,
                              void* d_out, int out_size)
{
    const float* x            = (const float*)d_in[0];
    const float* qkv_w        = (const float*)d_in[1];
    const float* qkv_b        = (const float*)d_in[2];
    const float* w1_write     = (const float*)d_in[3];
    const float* w2_write     = (const float*)d_in[4];
    const float* w1_read      = (const float*)d_in[5];
    const float* w2_read      = (const float*)d_in[6];
    const float* kv_geo_w     = (const float*)d_in[7];
    const float* out_w        = (const float*)d_in[8];
    const float* out_b        = (const float*)d_in[9];
    const float* kv_gate      = (const float*)d_in[10];
    const float* mem_scale    = (const float*)d_in[11];
    const float* decay_logits = (const float*)d_in[12];
    float* out = (float*)d_out;

    float *p_qkv, *p_kvgeo, *p_attno;
    cudaGetSymbolAddress((void**)&p_qkv,   g_qkv);
    cudaGetSymbolAddress((void**)&p_kvgeo, g_kvgeo);
    cudaGetSymbolAddress((void**)&p_attno, g_attno);

    // 1. qkv = x @ qkv_w + qkv_b            [2048, 3072]
    gemm_tf32<<<dim3(3072 / 64, TT / 128), 256>>>(x, qkv_w, qkv_b, p_qkv, TT, 3072, DD);
    // 2. kv_geo = x @ kv_geo_w              [2048, 2048]
    gemm_tf32<<<dim3(2048 / 64, TT / 128), 256>>>(x, kv_geo_w, nullptr, p_kvgeo, TT, 2048, DD);
    // 3. four 64-col projections in one launch
    gemm_proj<<<dim3(1, TT / 128, 4), 256>>>(x, w1_write, w2_write, w1_read, w2_read);
    // 4. Plucker lines
    lines_kernel<<<(TT * HH) / 256, 256>>>();
    // 5. decayed incidence^2 -> gram gate
    memscore<<<dim3(TT, HH), 128>>>(decay_logits, mem_scale);
    // 6. enhanced K/V
    enhance<<<(HH * TT * 64) / 256, 256>>>(kv_gate);
    // 7. causal flash attention
    attn<<<dim3(TT / 64, HH), 256>>>();
    // 8. final projection: out = attno @ out_w + out_b
    gemm_tf32<<<dim3(DD / 64, TT / 128), 256>>>(p_attno, out_w, out_b, out, TT, DD, DD);
}

// round 5
// speedup vs baseline: 3.7327x; 2.4347x over previous
#include <cuda_runtime.h>

#define TT 2048
#define DD 1024
#define HH 16

// ---------------- scratch (static device globals; no allocations) -------------
__device__ float g_qkv[TT * 3 * DD];     // [t][3*1024]  (q|k|v per token)
__device__ float g_kvgeo[TT * 2 * DD];   // [t][2*1024]  (k_geo|v_geo)
__device__ float g_proj[4 * TT * 64];    // P1|P2|R1|R2, each [t][64]
__device__ float g_jw[HH * 6 * TT];      // [h][c][t]    J6-applied write lines
__device__ float g_read[TT * HH * 6];    // [t][h][c]    read lines
__device__ float g_gate[HH * TT];        // [h][t]       gram gate
__device__ float g_kenh[HH * TT * 64];   // [h][t][d]
__device__ float g_venh[HH * TT * 64];   // [h][t][d]
__device__ float g_attno[TT * DD];       // [t][h*64+d]  attention output

// ---------------- tf32 helpers ----------------------------------------------
__device__ __forceinline__ unsigned f2tf(float f) {
    unsigned r;
    asm("cvt.rna.tf32.f32 %0, %1;" : "=r"(r) : "f"(f));
    return r;
}

__device__ __forceinline__ void mma_tf32(float* c, const unsigned* a, const unsigned* b) {
    asm volatile(
        "mma.sync.aligned.m16n8k8.row.col.f32.tf32.tf32.f32 "
        "{%0,%1,%2,%3}, {%4,%5,%6,%7}, {%8,%9}, {%0,%1,%2,%3};"
        : "+f"(c[0]), "+f"(c[1]), "+f"(c[2]), "+f"(c[3])
        : "r"(a[0]), "r"(a[1]), "r"(a[2]), "r"(a[3]), "r"(b[0]), "r"(b[1]));
}

// ---------------- tf32 GEMM body: C[M,N] = A[M,K] @ B[K,N] (+bias) ----------
#define A_ST 36
#define B_ST 72

__device__ __forceinline__ void gemm_body(
    const float* __restrict__ A, const float* __restrict__ B,
    const float* __restrict__ bias, float* __restrict__ C,
    int M, int N, int K)
{
    __shared__ unsigned As[128 * A_ST];
    __shared__ unsigned Bs[32 * B_ST];

    const int tid = threadIdx.x;
    const int lane = tid & 31, warp = tid >> 5;
    const int wm = (warp & 3) << 5;
    const int wn = (warp >> 2) << 5;
    const int m0 = blockIdx.y << 7, n0 = blockIdx.x << 6;
    const int lr = lane >> 2, lc = lane & 3;

    const int am = tid >> 3, ak = (tid & 7) << 2;
    const int bk = tid >> 4, bn = (tid & 15) << 2;

    const float* Aptr = A + (size_t)(m0 + am) * K + ak;
    const float* Bptr = B + (size_t)bk * N + n0 + bn;

    float4 ar[4], br[2];
#pragma unroll
    for (int i = 0; i < 4; i++) ar[i] = *(const float4*)(Aptr + (size_t)(i * 32) * K);
#pragma unroll
    for (int i = 0; i < 2; i++) br[i] = *(const float4*)(Bptr + (size_t)(i * 16) * N);

    float acc[2][4][4];
#pragma unroll
    for (int mi = 0; mi < 2; mi++)
#pragma unroll
        for (int ni = 0; ni < 4; ni++)
#pragma unroll
            for (int q = 0; q < 4; q++) acc[mi][ni][q] = 0.f;

    for (int kt = 0; kt < K; kt += 32) {
        __syncthreads();
#pragma unroll
        for (int i = 0; i < 4; i++) {
            unsigned* p = &As[(am + i * 32) * A_ST + ak];
            p[0] = f2tf(ar[i].x); p[1] = f2tf(ar[i].y);
            p[2] = f2tf(ar[i].z); p[3] = f2tf(ar[i].w);
        }
#pragma unroll
        for (int i = 0; i < 2; i++) {
            unsigned* p = &Bs[(bk + i * 16) * B_ST + bn];
            p[0] = f2tf(br[i].x); p[1] = f2tf(br[i].y);
            p[2] = f2tf(br[i].z); p[3] = f2tf(br[i].w);
        }
        __syncthreads();
        if (kt + 32 < K) {
#pragma unroll
            for (int i = 0; i < 4; i++)
                ar[i] = *(const float4*)(Aptr + (size_t)(i * 32) * K + (kt + 32));
#pragma unroll
            for (int i = 0; i < 2; i++)
                br[i] = *(const float4*)(Bptr + (size_t)(kt + 32 + i * 16) * N);
        }
#pragma unroll
        for (int kk = 0; kk < 32; kk += 8) {
            unsigned af[2][4], bf[4][2];
#pragma unroll
            for (int mi = 0; mi < 2; mi++) {
                const int row = wm + mi * 16 + lr;
                af[mi][0] = As[row * A_ST + kk + lc];
                af[mi][1] = As[(row + 8) * A_ST + kk + lc];
                af[mi][2] = As[row * A_ST + kk + 4 + lc];
                af[mi][3] = As[(row + 8) * A_ST + kk + 4 + lc];
            }
#pragma unroll
            for (int ni = 0; ni < 4; ni++) {
                const int col = wn + ni * 8 + lr;
                bf[ni][0] = Bs[(kk + lc) * B_ST + col];
                bf[ni][1] = Bs[(kk + 4 + lc) * B_ST + col];
            }
#pragma unroll
            for (int mi = 0; mi < 2; mi++)
#pragma unroll
                for (int ni = 0; ni < 4; ni++)
                    mma_tf32(acc[mi][ni], af[mi], bf[ni]);
        }
    }

#pragma unroll
    for (int mi = 0; mi < 2; mi++) {
#pragma unroll
        for (int ni = 0; ni < 4; ni++) {
            const int row = m0 + wm + mi * 16 + lr;
            const int col = n0 + wn + ni * 8 + (lc << 1);
            float b0 = 0.f, b1 = 0.f;
            if (bias) { b0 = bias[col]; b1 = bias[col + 1]; }
            float2 o0, o1;
            o0.x = acc[mi][ni][0] + b0; o0.y = acc[mi][ni][1] + b1;
            o1.x = acc[mi][ni][2] + b0; o1.y = acc[mi][ni][3] + b1;
            *(float2*)&C[(size_t)row * N + col] = o0;
            *(float2*)&C[(size_t)(row + 8) * N + col] = o1;
        }
    }
}

__global__ __launch_bounds__(256) void gemm_tf32(
    const float* __restrict__ A, const float* __restrict__ B,
    const float* __restrict__ bias, float* __restrict__ C,
    int M, int N, int K)
{
    gemm_body(A, B, bias, C, M, N, K);
}

__global__ __launch_bounds__(256) void gemm_proj(
    const float* __restrict__ x,
    const float* __restrict__ w0, const float* __restrict__ w1,
    const float* __restrict__ w2, const float* __restrict__ w3)
{
    const float* B = (blockIdx.z == 0) ? w0 : (blockIdx.z == 1) ? w1
                   : (blockIdx.z == 2) ? w2 : w3;
    float* C = g_proj + (size_t)blockIdx.z * TT * 64;
    gemm_body(x, B, nullptr, C, TT, 64, DD);
}

// ------------- Plucker lines from projections --------------------------------
__global__ __launch_bounds__(256) void lines_kernel()
{
    const int idx = blockIdx.x * 256 + threadIdx.x;   // T*H
    const int h = idx & (HH - 1), t = idx >> 4;
    const float* P1 = g_proj;
    const float* P2 = g_proj + TT * 64;
    const float* R1 = g_proj + 2 * TT * 64;
    const float* R2 = g_proj + 3 * TT * 64;

    float a0 = 0.f, a1 = 0.f, a2 = 0.f, a3 = 0.f;
    if (t > 0) {
        const float* p = P1 + (size_t)(t - 1) * 64 + h * 4;
        a0 = p[0]; a1 = p[1]; a2 = p[2]; a3 = p[3];
    }
    const float* p2 = P2 + (size_t)t * 64 + h * 4;
    float b0 = p2[0], b1 = p2[1], b2 = p2[2], b3 = p2[3];

    float L0 = a0 * b1 - a1 * b0;
    float L1 = a0 * b2 - a2 * b0;
    float L2 = a0 * b3 - a3 * b0;
    float L3 = a1 * b2 - a2 * b1;
    float L4 = a1 * b3 - a3 * b1;
    float L5 = a2 * b3 - a3 * b2;
    float n = sqrtf(L0 * L0 + L1 * L1 + L2 * L2 + L3 * L3 + L4 * L4 + L5 * L5);
    float inv = 1.f / fmaxf(n, 1e-12f);
    float* jw = g_jw + h * 6 * TT;
    jw[0 * TT + t] =  L5 * inv;
    jw[1 * TT + t] = -L4 * inv;
    jw[2 * TT + t] =  L3 * inv;
    jw[3 * TT + t] =  L2 * inv;
    jw[4 * TT + t] = -L1 * inv;
    jw[5 * TT + t] =  L0 * inv;

    const float* r1 = R1 + (size_t)t * 64 + h * 4;
    const float* r2 = R2 + (size_t)t * 64 + h * 4;
    a0 = r1[0]; a1 = r1[1]; a2 = r1[2]; a3 = r1[3];
    b0 = r2[0]; b1 = r2[1]; b2 = r2[2]; b3 = r2[3];
    L0 = a0 * b1 - a1 * b0;
    L1 = a0 * b2 - a2 * b0;
    L2 = a0 * b3 - a3 * b0;
    L3 = a1 * b2 - a2 * b1;
    L4 = a1 * b3 - a3 * b1;
    L5 = a2 * b3 - a3 * b2;
    n = sqrtf(L0 * L0 + L1 * L1 + L2 * L2 + L3 * L3 + L4 * L4 + L5 * L5);
    inv = 1.f / fmaxf(n, 1e-12f);
    float* rd = g_read + ((size_t)t * HH + h) * 6;
    rd[0] = L0 * inv; rd[1] = L1 * inv; rd[2] = L2 * inv;
    rd[3] = L3 * inv; rd[4] = L4 * inv; rd[5] = L5 * inv;
}

// ------------- mem_score / gram gate -----------------------------------------
__global__ __launch_bounds__(128) void memscore(
    const float* __restrict__ decay_logits, const float* __restrict__ mem_scale)
{
    const int t = blockIdx.x, h = blockIdx.y, tid = threadIdx.x;
    const float* rd = g_read + ((size_t)t * HH + h) * 6;
    const float r0 = rd[0], r1 = rd[1], r2 = rd[2], r3 = rd[3], r4 = rd[4], r5 = rd[5];

    const float logit = decay_logits[h];
    const float decay = 1.f / (1.f + expf(-logit));
    const float dlog = logf(decay);
    float w = expf((float)(tid + 1) * dlog);
    const float d128 = expf(128.f * dlog);

    const float* base = g_jw + h * 6 * TT;
    float partial = 0.f;
    for (int s = t - 1 - tid; s >= 0; s -= 128) {
        float inc = r0 * base[s] + r1 * base[TT + s] + r2 * base[2 * TT + s]
                  + r3 * base[3 * TT + s] + r4 * base[4 * TT + s] + r5 * base[5 * TT + s];
        partial += inc * inc * w;
        w *= d128;
    }
#pragma unroll
    for (int o = 16; o > 0; o >>= 1) partial += __shfl_xor_sync(0xffffffffu, partial, o);
    __shared__ float red[4];
    if ((tid & 31) == 0) red[tid >> 5] = partial;
    __syncthreads();
    if (tid == 0) {
        float ms = red[0] + red[1] + red[2] + red[3];
        g_gate[h * TT + t] = 1.f / (1.f + expf(-ms * mem_scale[h]));
    }
}

// ------------- k_enh / v_enh assembly ([h][t][d] layout) ---------------------
__global__ __launch_bounds__(256) void enhance(const float* __restrict__ kv_gate_p)
{
    const int idx = blockIdx.x * 256 + threadIdx.x;
    const int d = idx & 63, t = (idx >> 6) & (TT - 1), h = idx >> 17;
    const float gg = kv_gate_p[0] * g_gate[h * TT + t];
    const float kg = g_kvgeo[(size_t)t * 2 * DD + h * 64 + d];
    const float vg = g_kvgeo[(size_t)t * 2 * DD + DD + h * 64 + d];
    g_kenh[idx] = g_qkv[(size_t)t * 3 * DD + DD + h * 64 + d] + gg * kg;
    g_venh[idx] = g_qkv[(size_t)t * 3 * DD + 2 * DD + h * 64 + d] + gg * vg;
}

// ------------- causal flash attention, tf32 tensor cores ---------------------
// Block = (64-query tile, head), 4 warps, each warp owns 16 query rows.
// Ks buffer (stride 68) holds: Q staging -> K tile -> P tile (per iteration).
// Vs buffer (stride 72) holds the V tile.
#define KS_ST 68
#define VS_ST 72
__global__ __launch_bounds__(128) void attn()
{
    __shared__ unsigned Ks[64 * KS_ST];
    __shared__ unsigned Vs[64 * VS_ST];
    const int h = blockIdx.y, m0 = blockIdx.x << 6;
    const int tid = threadIdx.x, lane = tid & 31, warp = tid >> 5;
    const int lr = lane >> 2, lc = lane & 3;
    const int wm = warp << 4;

    // ---- stage Q (pre-scaled) and pull A fragments into registers ----
    for (int i = tid; i < 64 * 16; i += 128) {
        const int row = i >> 4, c4 = (i & 15) << 2;
        float4 v = *(const float4*)(g_qkv + (size_t)(m0 + row) * 3 * DD + h * 64 + c4);
        unsigned* p = &Ks[row * KS_ST + c4];
        p[0] = f2tf(v.x * 0.125f); p[1] = f2tf(v.y * 0.125f);
        p[2] = f2tf(v.z * 0.125f); p[3] = f2tf(v.w * 0.125f);
    }
    __syncthreads();
    unsigned qf[8][4];
#pragma unroll
    for (int kt = 0; kt < 8; kt++) {
        qf[kt][0] = Ks[(wm + lr) * KS_ST + kt * 8 + lc];
        qf[kt][1] = Ks[(wm + lr + 8) * KS_ST + kt * 8 + lc];
        qf[kt][2] = Ks[(wm + lr) * KS_ST + kt * 8 + 4 + lc];
        qf[kt][3] = Ks[(wm + lr + 8) * KS_ST + kt * 8 + 4 + lc];
    }

    float oacc[8][4];
#pragma unroll
    for (int ni = 0; ni < 8; ni++)
#pragma unroll
        for (int q = 0; q < 4; q++) oacc[ni][q] = 0.f;
    float mrun0 = -1e30f, mrun1 = -1e30f, lrun0 = 0.f, lrun1 = 0.f;

    for (int s0 = 0; s0 <= m0; s0 += 64) {
        __syncthreads();   // previous iteration's P/V reads complete
        for (int i = tid; i < 64 * 16; i += 128) {
            const int row = i >> 4, c4 = (i & 15) << 2;
            const size_t base = ((size_t)(h * TT + s0 + row)) << 6;
            float4 kv = *(const float4*)(g_kenh + base + c4);
            unsigned* pk = &Ks[row * KS_ST + c4];
            pk[0] = f2tf(kv.x); pk[1] = f2tf(kv.y); pk[2] = f2tf(kv.z); pk[3] = f2tf(kv.w);
            float4 vv = *(const float4*)(g_venh + base + c4);
            unsigned* pv = &Vs[row * VS_ST + c4];
            pv[0] = f2tf(vv.x); pv[1] = f2tf(vv.y); pv[2] = f2tf(vv.z); pv[3] = f2tf(vv.w);
        }
        __syncthreads();

        // ---- S = Q @ K^T ----
        float sacc[8][4];
#pragma unroll
        for (int ni = 0; ni < 8; ni++)
#pragma unroll
            for (int q = 0; q < 4; q++) sacc[ni][q] = 0.f;
#pragma unroll
        for (int kt = 0; kt < 8; kt++) {
            unsigned bf[8][2];
#pragma unroll
            for (int ni = 0; ni < 8; ni++) {
                const int col = ni * 8 + lr;
                bf[ni][0] = Ks[col * KS_ST + kt * 8 + lc];
                bf[ni][1] = Ks[col * KS_ST + kt * 8 + 4 + lc];
            }
#pragma unroll
            for (int ni = 0; ni < 8; ni++) mma_tf32(sacc[ni], qf[kt], bf[ni]);
        }

        // ---- causal mask (diagonal tile only) ----
        if (s0 == m0) {
            const int r0 = wm + lr, r1 = r0 + 8;
#pragma unroll
            for (int ni = 0; ni < 8; ni++) {
                const int c0 = ni * 8 + (lc << 1), c1 = c0 + 1;
                if (c0 > r0) sacc[ni][0] = -1e30f;
                if (c1 > r0) sacc[ni][1] = -1e30f;
                if (c0 > r1) sacc[ni][2] = -1e30f;
                if (c1 > r1) sacc[ni][3] = -1e30f;
            }
        }

        // ---- online softmax (rows lr and lr+8 per thread) ----
        float mx0 = -1e30f, mx1 = -1e30f;
#pragma unroll
        for (int ni = 0; ni < 8; ni++) {
            mx0 = fmaxf(mx0, fmaxf(sacc[ni][0], sacc[ni][1]));
            mx1 = fmaxf(mx1, fmaxf(sacc[ni][2], sacc[ni][3]));
        }
        mx0 = fmaxf(mx0, __shfl_xor_sync(0xffffffffu, mx0, 1));
        mx0 = fmaxf(mx0, __shfl_xor_sync(0xffffffffu, mx0, 2));
        mx1 = fmaxf(mx1, __shfl_xor_sync(0xffffffffu, mx1, 1));
        mx1 = fmaxf(mx1, __shfl_xor_sync(0xffffffffu, mx1, 2));

        const float mnew0 = fmaxf(mrun0, mx0), mnew1 = fmaxf(mrun1, mx1);
        const float corr0 = __expf(mrun0 - mnew0), corr1 = __expf(mrun1 - mnew1);
        mrun0 = mnew0; mrun1 = mnew1;

        __syncthreads();   // all warps done reading K from Ks before P overwrite

        float l0 = 0.f, l1 = 0.f;
#pragma unroll
        for (int ni = 0; ni < 8; ni++) {
            const float p0 = __expf(sacc[ni][0] - mnew0);
            const float p1 = __expf(sacc[ni][1] - mnew0);
            const float p2 = __expf(sacc[ni][2] - mnew1);
            const float p3 = __expf(sacc[ni][3] - mnew1);
            l0 += p0 + p1; l1 += p2 + p3;
            const int c = ni * 8 + (lc << 1);
            Ks[(wm + lr) * KS_ST + c]     = f2tf(p0);
            Ks[(wm + lr) * KS_ST + c + 1] = f2tf(p1);
            Ks[(wm + lr + 8) * KS_ST + c]     = f2tf(p2);
            Ks[(wm + lr + 8) * KS_ST + c + 1] = f2tf(p3);
        }
        l0 += __shfl_xor_sync(0xffffffffu, l0, 1);
        l0 += __shfl_xor_sync(0xffffffffu, l0, 2);
        l1 += __shfl_xor_sync(0xffffffffu, l1, 1);
        l1 += __shfl_xor_sync(0xffffffffu, l1, 2);
        lrun0 = lrun0 * corr0 + l0;
        lrun1 = lrun1 * corr1 + l1;
#pragma unroll
        for (int ni = 0; ni < 8; ni++) {
            oacc[ni][0] *= corr0; oacc[ni][1] *= corr0;
            oacc[ni][2] *= corr1; oacc[ni][3] *= corr1;
        }
        __syncwarp();   // each warp reads only its own 16 P rows

        // ---- O += P @ V ----
#pragma unroll
        for (int kt = 0; kt < 8; kt++) {
            unsigned af[4];
            af[0] = Ks[(wm + lr) * KS_ST + kt * 8 + lc];
            af[1] = Ks[(wm + lr + 8) * KS_ST + kt * 8 + lc];
            af[2] = Ks[(wm + lr) * KS_ST + kt * 8 + 4 + lc];
            af[3] = Ks[(wm + lr + 8) * KS_ST + kt * 8 + 4 + lc];
            unsigned bf[8][2];
#pragma unroll
            for (int ni = 0; ni < 8; ni++) {
                const int col = ni * 8 + lr;
                bf[ni][0] = Vs[(kt * 8 + lc) * VS_ST + col];
                bf[ni][1] = Vs[(kt * 8 + 4 + lc) * VS_ST + col];
            }
#pragma unroll
            for (int ni = 0; ni < 8; ni++) mma_tf32(oacc[ni], af, bf[ni]);
        }
    }

    // ---- epilogue ----
    const float inv0 = 1.f / lrun0, inv1 = 1.f / lrun1;
    const int r0 = m0 + wm + lr;
#pragma unroll
    for (int ni = 0; ni < 8; ni++) {
        const int c = h * 64 + ni * 8 + (lc << 1);
        float2 o0, o1;
        o0.x = oacc[ni][0] * inv0; o0.y = oacc[ni][1] * inv0;
        o1.x = oacc[ni][2] * inv1; o1.y = oacc[ni][3] * inv1;
        *(float2*)&g_attno[(size_t)r0 * DD + c] = o0;
        *(float2*)&g_attno[(size_t)(r0 + 8) * DD + c] = o1;
    }
}

// -----------------------------------------------------------------------------
extern "C" void kernel_launch(void* const* d_in, const int* in_sizes, int n_in,
                              void* d_out, int out_size)
{
    const float* x            = (const float*)d_in[0];
    const float* qkv_w        = (const float*)d_in[1];
    const float* qkv_b        = (const float*)d_in[2];
    const float* w1_write     = (const float*)d_in[3];
    const float* w2_write     = (const float*)d_in[4];
    const float* w1_read      = (const float*)d_in[5];
    const float* w2_read      = (const float*)d_in[6];
    const float* kv_geo_w     = (const float*)d_in[7];
    const float* out_w        = (const float*)d_in[8];
    const float* out_b        = (const float*)d_in[9];
    const float* kv_gate      = (const float*)d_in[10];
    const float* mem_scale    = (const float*)d_in[11];
    const float* decay_logits = (const float*)d_in[12];
    float* out = (float*)d_out;

    float *p_qkv, *p_kvgeo, *p_attno;
    cudaGetSymbolAddress((void**)&p_qkv,   g_qkv);
    cudaGetSymbolAddress((void**)&p_kvgeo, g_kvgeo);
    cudaGetSymbolAddress((void**)&p_attno, g_attno);

    // 1. qkv = x @ qkv_w + qkv_b            [2048, 3072]
    gemm_tf32<<<dim3(3072 / 64, TT / 128), 256>>>(x, qkv_w, qkv_b, p_qkv, TT, 3072, DD);
    // 2. kv_geo = x @ kv_geo_w              [2048, 2048]
    gemm_tf32<<<dim3(2048 / 64, TT / 128), 256>>>(x, kv_geo_w, nullptr, p_kvgeo, TT, 2048, DD);
    // 3. four 64-col projections in one launch
    gemm_proj<<<dim3(1, TT / 128, 4), 256>>>(x, w1_write, w2_write, w1_read, w2_read);
    // 4. Plucker lines
    lines_kernel<<<(TT * HH) / 256, 256>>>();
    // 5. decayed incidence^2 -> gram gate
    memscore<<<dim3(TT, HH), 128>>>(decay_logits, mem_scale);
    // 6. enhanced K/V
    enhance<<<(HH * TT * 64) / 256, 256>>>(kv_gate);
    // 7. causal flash attention (tf32 mma)
    attn<<<dim3(TT / 64, HH), 128>>>();
    // 8. final projection: out = attno @ out_w + out_b
    gemm_tf32<<<dim3(DD / 64, TT / 128), 256>>>(p_attno, out_w, out_b, out, TT, DD, DD);
}